// round 4
// baseline (speedup 1.0000x reference)
#include <cuda_runtime.h>
#include <math.h>
#include <stdint.h>

// ---------------------------------------------------------------------------
// Vit_Spatial_Map (sm_103a harness, PTX target sm_103 => legacy mma.sync only).
// TF32 mma.sync m16n8k8, fp32 accumulate, 2-stage smem pipeline.
// B=8, Np=1024, DIM=256, HEADS=4, DH=64, patch_dim=4096, M=8192.
//   emb  = patches @ W_embed^T + b_embed + pos        (8192 x 256, K=4096)
//   q    = emb @ Wq_avg^T (row-mean of Wq per head)   (8192 x 4)
//   k    = sigmoid(q @ Wk^T)                          (32 x 1024)
//   kv   = (emb @ Wv^T) * k                           (8192 x 256, K=256)
//   out  = fold(kv @ Wout^T + b_out)                  (8192 x 4096, K=256)
// ---------------------------------------------------------------------------

static __device__ float g_emb[8192 * 256];
static __device__ float g_kv[8192 * 256];
static __device__ float g_wqavg[4 * 256];
static __device__ float g_q[32 * 1024];
static __device__ float g_k[32 * 1024];

enum { MODE_EMBED = 0, MODE_KV = 1, MODE_OUT = 2 };

__device__ __forceinline__ uint32_t f2tf32(float f) {
    uint32_t u;
    asm("cvt.rna.tf32.f32 %0, %1;" : "=r"(u) : "f"(f));
    return u;
}
__device__ __forceinline__ void mma_tf32(float* c, const uint32_t* a, const uint32_t* b) {
    asm volatile(
        "mma.sync.aligned.m16n8k8.row.col.f32.tf32.tf32.f32 "
        "{%0,%1,%2,%3}, {%4,%5,%6,%7}, {%8,%9}, {%0,%1,%2,%3};"
        : "+f"(c[0]), "+f"(c[1]), "+f"(c[2]), "+f"(c[3])
        : "r"(a[0]), "r"(a[1]), "r"(a[2]), "r"(a[3]), "r"(b[0]), "r"(b[1]));
}

// C(M x N) = A(M x K) * B(N x K)^T. BM=128, BN=128, BK=32, 256 threads.
// Warp grid 4(m) x 2(n); warp tile 32 x 64 = (2 x m16) x (8 x n8).
// Double-buffered smem, one __syncthreads per K-tile.
template <int MODE, int K>
__global__ __launch_bounds__(256) void gemm_mma(
    const float* __restrict__ Ap, const float* __restrict__ Bp,
    float* __restrict__ Cp, const float* __restrict__ bias,
    const float* __restrict__ pos)
{
    extern __shared__ uint32_t smem_u[];          // 2 x As[32][132] + 2 x Bs[32][132]
    constexpr int TSZ = 32 * 132;
    uint32_t* const Abuf[2] = { smem_u,            smem_u + TSZ };
    uint32_t* const Bbuf[2] = { smem_u + 2 * TSZ,  smem_u + 3 * TSZ };

    const int tid   = threadIdx.x;
    const int mBase = blockIdx.y * 128;
    const int nBase = blockIdx.x * 128;

    const int warp = tid >> 5;
    const int lane = tid & 31;
    const int g    = lane >> 2;
    const int tg   = lane & 3;
    const int mw   = (warp & 3) * 32;
    const int nw   = (warp >> 2) * 64;

    const float* A = (MODE == MODE_EMBED) ? Ap : (MODE == MODE_KV ? g_emb : g_kv);

    const int mq = tid & 31;   // *4 -> 128 rows staged
    const int kq = tid >> 5;   // *4 -> 32 k staged

    float acc[2][8][4];
#pragma unroll
    for (int i = 0; i < 2; i++)
#pragma unroll
        for (int j = 0; j < 8; j++)
#pragma unroll
            for (int l = 0; l < 4; l++) acc[i][j][l] = 0.0f;

    float4 av[4], bv[4];

    // ---- tile loader (gmem -> regs) ----
    auto load_tile = [&](int kt) {
        const int ka = kt * 32 + kq * 4;
        if (MODE == MODE_EMBED) {
            const int c  = ka >> 6;
            const int kh = (ka >> 3) & 7;
            const int kw = ka & 7;
#pragma unroll
            for (int r = 0; r < 4; r++) {
                const int m  = mBase + mq * 4 + r;
                const int bn = m >> 10, n = m & 1023;
                const int ph = n >> 5, pw = n & 31;
                const size_t idx =
                    ((((size_t)bn * 64 + c) * 256) + (size_t)(ph * 8 + kh)) * 256
                    + (size_t)(pw * 8 + kw);
                av[r] = *reinterpret_cast<const float4*>(A + idx);
            }
        } else {
#pragma unroll
            for (int r = 0; r < 4; r++)
                av[r] = *reinterpret_cast<const float4*>(
                    A + (size_t)(mBase + mq * 4 + r) * K + ka);
        }
#pragma unroll
        for (int r = 0; r < 4; r++)
            bv[r] = *reinterpret_cast<const float4*>(
                Bp + (size_t)(nBase + mq * 4 + r) * K + ka);
    };

    // ---- regs -> smem (4x4 transpose + tf32 round) ----
    auto store_tile = [&](int s) {
        uint32_t* As = Abuf[s];
        uint32_t* Bs = Bbuf[s];
        const float* a0 = &av[0].x; const float* a1 = &av[1].x;
        const float* a2 = &av[2].x; const float* a3 = &av[3].x;
        const float* b0 = &bv[0].x; const float* b1 = &bv[1].x;
        const float* b2 = &bv[2].x; const float* b3 = &bv[3].x;
#pragma unroll
        for (int i = 0; i < 4; i++) {
            uint4 ua = make_uint4(f2tf32(a0[i]), f2tf32(a1[i]),
                                  f2tf32(a2[i]), f2tf32(a3[i]));
            uint4 ub = make_uint4(f2tf32(b0[i]), f2tf32(b1[i]),
                                  f2tf32(b2[i]), f2tf32(b3[i]));
            *reinterpret_cast<uint4*>(&As[(kq * 4 + i) * 132 + mq * 4]) = ua;
            *reinterpret_cast<uint4*>(&Bs[(kq * 4 + i) * 132 + mq * 4]) = ub;
        }
    };

    // ---- compute one K-tile from buffer s ----
    auto compute_tile = [&](int s) {
        const uint32_t* As = Abuf[s];
        const uint32_t* Bs = Bbuf[s];
#pragma unroll
        for (int ks = 0; ks < 4; ks++) {
            const uint32_t* A0 = &As[(ks * 8 + tg) * 132];
            const uint32_t* A4 = &As[(ks * 8 + tg + 4) * 132];
            const uint32_t* B0 = &Bs[(ks * 8 + tg) * 132];
            const uint32_t* B4 = &Bs[(ks * 8 + tg + 4) * 132];
            uint32_t a[2][4], b[8][2];
#pragma unroll
            for (int mt = 0; mt < 2; mt++) {
                const int mo = mw + mt * 16 + g;
                a[mt][0] = A0[mo];     a[mt][1] = A0[mo + 8];
                a[mt][2] = A4[mo];     a[mt][3] = A4[mo + 8];
            }
#pragma unroll
            for (int nt = 0; nt < 8; nt++) {
                const int no = nw + nt * 8 + g;
                b[nt][0] = B0[no];     b[nt][1] = B4[no];
            }
#pragma unroll
            for (int mt = 0; mt < 2; mt++)
#pragma unroll
                for (int nt = 0; nt < 8; nt++)
                    mma_tf32(acc[mt][nt], a[mt], b[nt]);
        }
    };

    constexpr int NT = K / 32;
    load_tile(0);
    store_tile(0);
    __syncthreads();

    for (int kt = 0; kt < NT; kt++) {
        const int s = kt & 1;
        if (kt + 1 < NT) load_tile(kt + 1);     // LDG overlaps compute
        compute_tile(s);
        if (kt + 1 < NT) store_tile(1 - s);     // idle buffer: no pre-sync needed
        __syncthreads();
    }

    // ---------------- epilogue ----------------
#pragma unroll
    for (int mt = 0; mt < 2; mt++) {
#pragma unroll
        for (int half = 0; half < 2; half++) {
            const int m  = mBase + mw + mt * 16 + g + half * 8;
            const int bn = m >> 10, n = m & 1023;
            float kf;
            if (MODE == MODE_KV) {
                const int h = (nBase + nw) >> 6;  // nw multiple of 64
                kf = g_k[(bn * 4 + h) * 1024 + n];
            }
#pragma unroll
            for (int nt = 0; nt < 8; nt++) {
                const int col = nBase + nw + nt * 8 + tg * 2;
                float vx = acc[mt][nt][half * 2 + 0];
                float vy = acc[mt][nt][half * 2 + 1];

                if (MODE == MODE_EMBED) {
                    const float* pr = pos + (size_t)n * 256 + col;
                    vx += bias[col + 0] + pr[0];
                    vy += bias[col + 1] + pr[1];
                    *reinterpret_cast<float2*>(&g_emb[(size_t)m * 256 + col]) =
                        make_float2(vx, vy);
                } else if (MODE == MODE_KV) {
                    vx *= kf; vy *= kf;
                    *reinterpret_cast<float2*>(&g_kv[(size_t)m * 256 + col]) =
                        make_float2(vx, vy);
                } else {
                    vx += bias[col + 0];
                    vy += bias[col + 1];
                    const int ph = n >> 5, pw = n & 31;
                    const int c  = col >> 6;
                    const int kh = (col >> 3) & 7;
                    const int kw = col & 7;
                    const size_t idx =
                        ((((size_t)bn * 64 + c) * 256) + (size_t)(ph * 8 + kh)) * 256
                        + (size_t)(pw * 8 + kw);
                    *reinterpret_cast<float2*>(Cp + idx) = make_float2(vx, vy);
                }
            }
        }
    }
}

// Wq_avg[h][j] = mean over d of Wq[h*64+d][j]
__global__ void k_wqavg(const float* __restrict__ Wq)
{
    const int h = blockIdx.x, j = threadIdx.x;
    float s = 0.0f;
#pragma unroll 8
    for (int d = 0; d < 64; d++) s += Wq[(size_t)(h * 64 + d) * 256 + j];
    g_wqavg[h * 256 + j] = s * (1.0f / 64.0f);
}

// q[bn,h,n] = emb[m,:] . wqavg[h,:]
__global__ __launch_bounds__(128) void k_q()
{
    const int m = blockIdx.x;
    const int w = threadIdx.x >> 5, lane = threadIdx.x & 31;
    const float* e  = g_emb + (size_t)m * 256;
    const float* wa = g_wqavg + w * 256;
    float s = 0.0f;
#pragma unroll
    for (int t = 0; t < 8; t++) s += e[lane + t * 32] * wa[lane + t * 32];
#pragma unroll
    for (int off = 16; off > 0; off >>= 1)
        s += __shfl_xor_sync(0xFFFFFFFFu, s, off);
    if (lane == 0) {
        const int bn = m >> 10, n = m & 1023;
        g_q[(bn * 4 + w) * 1024 + n] = s;
    }
}

// k = sigmoid(q @ Wk^T): q fully staged in smem; warp per Wk row, all 32 bh.
__global__ __launch_bounds__(256) void k_sig2(const float* __restrict__ Wk)
{
    extern __shared__ float4 qs4[];  // [32][258] float4
    const int tid = threadIdx.x, warp = tid >> 5, lane = tid & 31;
    const float4* gq = reinterpret_cast<const float4*>(g_q);
#pragma unroll
    for (int i = 0; i < 32; i++) {
        const int e = tid + 256 * i;          // 8192 float4 total
        qs4[(e >> 8) * 258 + (e & 255)] = gq[e];
    }
    __syncthreads();

    const int m = blockIdx.x * 8 + warp;
    float4 wr[8];
    const float4* wk4 = reinterpret_cast<const float4*>(Wk + (size_t)m * 1024);
#pragma unroll
    for (int j = 0; j < 8; j++) wr[j] = wk4[j * 32 + lane];

    for (int bh = 0; bh < 32; bh++) {
        float s = 0.0f;
#pragma unroll
        for (int j = 0; j < 8; j++) {
            const float4 q = qs4[bh * 258 + j * 32 + lane];
            s += q.x * wr[j].x + q.y * wr[j].y + q.z * wr[j].z + q.w * wr[j].w;
        }
#pragma unroll
        for (int o = 16; o > 0; o >>= 1) s += __shfl_xor_sync(0xFFFFFFFFu, s, o);
        if (lane == 0) g_k[bh * 1024 + m] = 1.0f / (1.0f + expf(-s));
    }
}

extern "C" void kernel_launch(void* const* d_in, const int* in_sizes, int n_in,
                              void* d_out, int out_size)
{
    const float* x    = (const float*)d_in[0];
    const float* Wemb = (const float*)d_in[1];
    const float* bemb = (const float*)d_in[2];
    const float* pos  = (const float*)d_in[3];
    const float* Wq   = (const float*)d_in[4];
    const float* Wk   = (const float*)d_in[5];
    const float* Wv   = (const float*)d_in[6];
    const float* Wout = (const float*)d_in[7];
    const float* bout = (const float*)d_in[8];
    float* out = (float*)d_out;

    const int SM_GEMM = 4 * 32 * 132 * 4;   // 67584 B
    const int SM_SIG  = 32 * 258 * 16;      // 132096 B

    cudaFuncSetAttribute(gemm_mma<MODE_EMBED, 4096>,
                         cudaFuncAttributeMaxDynamicSharedMemorySize, SM_GEMM);
    cudaFuncSetAttribute(gemm_mma<MODE_KV, 256>,
                         cudaFuncAttributeMaxDynamicSharedMemorySize, SM_GEMM);
    cudaFuncSetAttribute(gemm_mma<MODE_OUT, 256>,
                         cudaFuncAttributeMaxDynamicSharedMemorySize, SM_GEMM);
    cudaFuncSetAttribute(k_sig2,
                         cudaFuncAttributeMaxDynamicSharedMemorySize, SM_SIG);

    gemm_mma<MODE_EMBED, 4096><<<dim3(2, 64), 256, SM_GEMM>>>(
        x, Wemb, nullptr, bemb, pos);
    k_wqavg<<<4, 256>>>(Wq);
    k_q<<<8192, 128>>>();
    k_sig2<<<128, 256, SM_SIG>>>(Wk);
    gemm_mma<MODE_KV, 256><<<dim3(2, 64), 256, SM_GEMM>>>(
        nullptr, Wv, nullptr, nullptr, nullptr);
    gemm_mma<MODE_OUT, 256><<<dim3(32, 64), 256, SM_GEMM>>>(
        nullptr, Wout, out, bout, nullptr);
}

// round 5
// speedup vs baseline: 2.2568x; 2.2568x over previous
#include <cuda_runtime.h>
#include <cuda_fp16.h>
#include <math.h>
#include <stdint.h>

// ---------------------------------------------------------------------------
// Vit_Spatial_Map (sm_103 PTX target => legacy mma.sync path).
// FP16 mma.sync m16n8k16, fp32 accumulate (fp16 mantissa == tf32 mantissa).
// B=8, Np=1024, DIM=256, HEADS=4, DH=64, patch_dim=4096, M=8192.
//   emb  = patches @ W_embed^T + b_embed + pos        (8192 x 256, K=4096)
//   q    = emb @ Wq_avg^T (row-mean of Wq per head)   (8192 x 4)
//   k    = sigmoid(q @ Wk^T)                          (32 x 1024)
//   kv   = (emb @ Wv^T) * k                           (8192 x 256, K=256)
//   out  = fold(kv @ Wout^T + b_out)                  (8192 x 4096, K=256)
// ---------------------------------------------------------------------------

static __device__ float g_emb[8192 * 256];
static __device__ float g_kv[8192 * 256];
static __device__ float g_wqavg[4 * 256];
static __device__ float g_q[32 * 1024];
static __device__ float g_k[32 * 1024];

enum { MODE_EMBED = 0, MODE_KV = 1, MODE_OUT = 2 };

__device__ __forceinline__ uint32_t pack_h2(float x, float y) {
    const __half2 h = __floats2half2_rn(x, y);
    return *reinterpret_cast<const uint32_t*>(&h);
}
__device__ __forceinline__ void mma_f16(float* c, const uint32_t* a, const uint32_t* b) {
    asm volatile(
        "mma.sync.aligned.m16n8k16.row.col.f32.f16.f16.f32 "
        "{%0,%1,%2,%3}, {%4,%5,%6,%7}, {%8,%9}, {%0,%1,%2,%3};"
        : "+f"(c[0]), "+f"(c[1]), "+f"(c[2]), "+f"(c[3])
        : "r"(a[0]), "r"(a[1]), "r"(a[2]), "r"(a[3]), "r"(b[0]), "r"(b[1]));
}

// C(M x N) = A(M x K) * B(N x K)^T.  BM=128, BN=128, BK=32, 256 threads.
// Warp grid 4(m) x 2(n); warp tile 32 x 64 = (2 x m16) x (8 x n8), 2 k16/tile.
// SMEM: halves as [row][16 words], XOR swizzle word ^= (row&7)*2 => LDS
// fragment fetches hit 32 distinct banks (verified per lane-group algebra).
template <int MODE, int K>
__global__ __launch_bounds__(256) void gemm_h(
    const float* __restrict__ Ap, const float* __restrict__ Bp,
    float* __restrict__ Cp, const float* __restrict__ bias,
    const float* __restrict__ pos)
{
    __shared__ __align__(16) uint32_t As[2][128 * 16];  // 8KB per stage
    __shared__ __align__(16) uint32_t Bs[2][128 * 16];

    const int tid   = threadIdx.x;
    const int mBase = blockIdx.y * 128;
    const int nBase = blockIdx.x * 128;

    const int warp = tid >> 5;
    const int lane = tid & 31;
    const int g    = lane >> 2;
    const int tg   = lane & 3;
    const int mw   = (warp & 3) * 32;
    const int nw   = (warp >> 2) * 64;

    const float* A = (MODE == MODE_EMBED) ? Ap : (MODE == MODE_KV ? g_emb : g_kv);

    float acc[2][8][4];
#pragma unroll
    for (int i = 0; i < 2; i++)
#pragma unroll
        for (int j = 0; j < 8; j++)
#pragma unroll
            for (int l = 0; l < 4; l++) acc[i][j][l] = 0.0f;

    float4 av[4], bv[4];

    // ---- gmem -> regs (coalesced float4; embed gathers patches) ----
    auto load_tile = [&](int kt) {
        const int kbase = kt * 32;
#pragma unroll
        for (int i = 0; i < 4; i++) {
            const int f   = tid + 256 * i;
            const int row = f >> 3;       // 0..127
            const int k4  = f & 7;        // float4 index within 32 k
            const int ka  = kbase + k4 * 4;
            if (MODE == MODE_EMBED) {
                const int c  = ka >> 6;
                const int kh = (ka >> 3) & 7;
                const int kw = ka & 7;
                const int m  = mBase + row;
                const int bn = m >> 10, n = m & 1023;
                const int ph = n >> 5, pw = n & 31;
                const size_t idx =
                    ((((size_t)bn * 64 + c) * 256) + (size_t)(ph * 8 + kh)) * 256
                    + (size_t)(pw * 8 + kw);
                av[i] = *reinterpret_cast<const float4*>(A + idx);
            } else {
                av[i] = *reinterpret_cast<const float4*>(
                    A + (size_t)(mBase + row) * K + ka);
            }
            bv[i] = *reinterpret_cast<const float4*>(
                Bp + (size_t)(nBase + row) * K + ka);
        }
    };

    // ---- regs -> smem (f32 -> f16 pack, swizzled) ----
    auto store_tile = [&](int s) {
#pragma unroll
        for (int i = 0; i < 4; i++) {
            const int f   = tid + 256 * i;
            const int row = f >> 3;
            const int k4  = f & 7;
            const int wo  = (k4 * 2) ^ ((row & 7) * 2);  // even => uint2-aligned
            const uint2 ua = make_uint2(pack_h2(av[i].x, av[i].y),
                                        pack_h2(av[i].z, av[i].w));
            const uint2 ub = make_uint2(pack_h2(bv[i].x, bv[i].y),
                                        pack_h2(bv[i].z, bv[i].w));
            *reinterpret_cast<uint2*>(&As[s][row * 16 + wo]) = ua;
            *reinterpret_cast<uint2*>(&Bs[s][row * 16 + wo]) = ub;
        }
    };

    // ---- compute one K-tile (2 x k16) ----
    auto compute_tile = [&](int s) {
        const int sw = g * 2;  // (row & 7) == g for all fragment rows here
#pragma unroll
        for (int ks = 0; ks < 2; ks++) {
            const int w0 = (ks * 8 + tg) ^ sw;
            const int w2 = (ks * 8 + tg + 4) ^ sw;
            uint32_t a[2][4], b[8][2];
#pragma unroll
            for (int mt = 0; mt < 2; mt++) {
                const uint32_t* R0 = &As[s][(mw + mt * 16 + g) * 16];
                const uint32_t* R8 = R0 + 8 * 16;
                a[mt][0] = R0[w0];  a[mt][1] = R8[w0];
                a[mt][2] = R0[w2];  a[mt][3] = R8[w2];
            }
#pragma unroll
            for (int nt = 0; nt < 8; nt++) {
                const uint32_t* Rn = &Bs[s][(nw + nt * 8 + g) * 16];
                b[nt][0] = Rn[w0];  b[nt][1] = Rn[w2];
            }
#pragma unroll
            for (int mt = 0; mt < 2; mt++)
#pragma unroll
                for (int nt = 0; nt < 8; nt++)
                    mma_f16(acc[mt][nt], a[mt], b[nt]);
        }
    };

    constexpr int NT = K / 32;
    load_tile(0);
    store_tile(0);
    __syncthreads();

    for (int kt = 0; kt < NT; kt++) {
        const int s = kt & 1;
        if (kt + 1 < NT) load_tile(kt + 1);
        compute_tile(s);
        if (kt + 1 < NT) store_tile(1 - s);
        __syncthreads();
    }

    // ---------------- epilogue ----------------
#pragma unroll
    for (int mt = 0; mt < 2; mt++) {
#pragma unroll
        for (int half = 0; half < 2; half++) {
            const int m  = mBase + mw + mt * 16 + g + half * 8;
            const int bn = m >> 10, n = m & 1023;
            float kf;
            if (MODE == MODE_KV) {
                const int h = (nBase + nw) >> 6;  // nw multiple of 64
                kf = g_k[(bn * 4 + h) * 1024 + n];
            }
#pragma unroll
            for (int nt = 0; nt < 8; nt++) {
                const int col = nBase + nw + nt * 8 + tg * 2;
                float vx = acc[mt][nt][half * 2 + 0];
                float vy = acc[mt][nt][half * 2 + 1];

                if (MODE == MODE_EMBED) {
                    const float* pr = pos + (size_t)n * 256 + col;
                    vx += bias[col + 0] + pr[0];
                    vy += bias[col + 1] + pr[1];
                    *reinterpret_cast<float2*>(&g_emb[(size_t)m * 256 + col]) =
                        make_float2(vx, vy);
                } else if (MODE == MODE_KV) {
                    vx *= kf; vy *= kf;
                    *reinterpret_cast<float2*>(&g_kv[(size_t)m * 256 + col]) =
                        make_float2(vx, vy);
                } else {
                    vx += bias[col + 0];
                    vy += bias[col + 1];
                    const int ph = n >> 5, pw = n & 31;
                    const int c  = col >> 6;
                    const int kh = (col >> 3) & 7;
                    const int kw = col & 7;
                    const size_t idx =
                        ((((size_t)bn * 64 + c) * 256) + (size_t)(ph * 8 + kh)) * 256
                        + (size_t)(pw * 8 + kw);
                    *reinterpret_cast<float2*>(Cp + idx) = make_float2(vx, vy);
                }
            }
        }
    }
}

// Wq_avg[h][j] = mean over d of Wq[h*64+d][j]
__global__ void k_wqavg(const float* __restrict__ Wq)
{
    const int h = blockIdx.x, j = threadIdx.x;
    float s = 0.0f;
#pragma unroll 8
    for (int d = 0; d < 64; d++) s += Wq[(size_t)(h * 64 + d) * 256 + j];
    g_wqavg[h * 256 + j] = s * (1.0f / 64.0f);
}

// q[bn,h,n] = emb[m,:] . wqavg[h,:]
__global__ __launch_bounds__(128) void k_q()
{
    const int m = blockIdx.x;
    const int w = threadIdx.x >> 5, lane = threadIdx.x & 31;
    const float* e  = g_emb + (size_t)m * 256;
    const float* wa = g_wqavg + w * 256;
    float s = 0.0f;
#pragma unroll
    for (int t = 0; t < 8; t++) s += e[lane + t * 32] * wa[lane + t * 32];
#pragma unroll
    for (int off = 16; off > 0; off >>= 1)
        s += __shfl_xor_sync(0xFFFFFFFFu, s, off);
    if (lane == 0) {
        const int bn = m >> 10, n = m & 1023;
        g_q[(bn * 4 + w) * 1024 + n] = s;
    }
}

// k = sigmoid(q @ Wk^T): q fully staged in smem; warp per Wk row, all 32 bh.
__global__ __launch_bounds__(256) void k_sig2(const float* __restrict__ Wk)
{
    extern __shared__ float4 qs4[];  // [32][258] float4
    const int tid = threadIdx.x, warp = tid >> 5, lane = tid & 31;
    const float4* gq = reinterpret_cast<const float4*>(g_q);
#pragma unroll
    for (int i = 0; i < 32; i++) {
        const int e = tid + 256 * i;          // 8192 float4 total
        qs4[(e >> 8) * 258 + (e & 255)] = gq[e];
    }
    __syncthreads();

    const int m = blockIdx.x * 8 + warp;
    float4 wr[8];
    const float4* wk4 = reinterpret_cast<const float4*>(Wk + (size_t)m * 1024);
#pragma unroll
    for (int j = 0; j < 8; j++) wr[j] = wk4[j * 32 + lane];

    for (int bh = 0; bh < 32; bh++) {
        float s = 0.0f;
#pragma unroll
        for (int j = 0; j < 8; j++) {
            const float4 q = qs4[bh * 258 + j * 32 + lane];
            s += q.x * wr[j].x + q.y * wr[j].y + q.z * wr[j].z + q.w * wr[j].w;
        }
#pragma unroll
        for (int o = 16; o > 0; o >>= 1) s += __shfl_xor_sync(0xFFFFFFFFu, s, o);
        if (lane == 0) g_k[bh * 1024 + m] = 1.0f / (1.0f + expf(-s));
    }
}

extern "C" void kernel_launch(void* const* d_in, const int* in_sizes, int n_in,
                              void* d_out, int out_size)
{
    const float* x    = (const float*)d_in[0];
    const float* Wemb = (const float*)d_in[1];
    const float* bemb = (const float*)d_in[2];
    const float* pos  = (const float*)d_in[3];
    const float* Wq   = (const float*)d_in[4];
    const float* Wk   = (const float*)d_in[5];
    const float* Wv   = (const float*)d_in[6];
    const float* Wout = (const float*)d_in[7];
    const float* bout = (const float*)d_in[8];
    float* out = (float*)d_out;

    const int SM_SIG = 32 * 258 * 16;  // 132096 B
    cudaFuncSetAttribute(k_sig2,
                         cudaFuncAttributeMaxDynamicSharedMemorySize, SM_SIG);

    gemm_h<MODE_EMBED, 4096><<<dim3(2, 64), 256>>>(x, Wemb, nullptr, bemb, pos);
    k_wqavg<<<4, 256>>>(Wq);
    k_q<<<8192, 128>>>();
    k_sig2<<<128, 256, SM_SIG>>>(Wk);
    gemm_h<MODE_KV, 256><<<dim3(2, 64), 256>>>(nullptr, Wv, nullptr, nullptr, nullptr);
    gemm_h<MODE_OUT, 256><<<dim3(32, 64), 256>>>(nullptr, Wout, out, bout, nullptr);
}